// round 11
// baseline (speedup 1.0000x reference)
#include <cuda_runtime.h>
#include <math.h>

#define BB    64
#define TT    256
#define WW    20
#define NP    6
#define NT    12
#define CH    32
#define LL1   18
#define LL2   16
#define PROJD 64
#define GATES 256
#define NWIN  (BB*TT)   // 16384

#define GRID_BLOCKS 148
#define NTHREADS    512
#define LSTM_BLOCKS 32
#define ENC_WARPS   16

typedef unsigned long long ull;

// Scratch (device globals per allocation rules)
__device__ float    g_xg[NWIN * GATES];   // 16 MB: precomputed input gates
__device__ unsigned g_prog[TT];           // completed windows per timestep
__device__ unsigned g_ticket;             // encode work ticket (in windows)

// ---- packed f32x2 helpers ---------------------------------------------------
__device__ __forceinline__ ull pk2(float lo, float hi) {
    ull r; asm("mov.b64 %0, {%1, %2};" : "=l"(r) : "f"(lo), "f"(hi)); return r;
}
__device__ __forceinline__ float2 unpk(ull a) {
    float2 v; asm("mov.b64 {%0, %1}, %2;" : "=f"(v.x), "=f"(v.y) : "l"(a)); return v;
}
__device__ __forceinline__ void fma2(ull& d, ull a, ull b) {
    asm("fma.rn.f32x2 %0, %1, %2, %0;" : "+l"(d) : "l"(a), "l"(b));
}
__device__ __forceinline__ ull add2(ull a, ull b) {
    ull r; asm("add.rn.f32x2 %0, %1, %2;" : "=l"(r) : "l"(a), "l"(b)); return r;
}

// ---- HW tanh-based activations ---------------------------------------------
__device__ __forceinline__ float tanhx(float x) {
    float y; asm("tanh.approx.f32 %0, %1;" : "=f"(y) : "f"(x)); return y;
}
__device__ __forceinline__ float sig_t(float x) {
    return fmaf(tanhx(0.5f * x), 0.5f, 0.5f);
}

// ---- acquire/release primitives --------------------------------------------
__device__ __forceinline__ unsigned ld_acq(const unsigned* p) {
    unsigned v;
    asm volatile("ld.acquire.gpu.global.b32 %0, [%1];" : "=r"(v) : "l"(p));
    return v;
}
__device__ __forceinline__ void red_rel_add(unsigned* p, unsigned v) {
    asm volatile("red.release.gpu.global.add.u32 [%0], %1;" :: "l"(p), "r"(v));
}
__device__ __forceinline__ float ld_strong(const float* p) {
    float v;
    asm volatile("ld.global.f32 %0, [%1];" : "=f"(v) : "l"(p));
    return v;
}

// ---- encoder shared memory layout (floats) ----------------------------------
#define S_W1P   0
#define S_W2P   (S_W1P + 576)
#define S_W1T   (S_W2P + 3072)
#define S_W2T   (S_W1T + 1152)
#define S_PRWP  (S_W2T + 3072)
#define S_WIHP  (S_PRWP + 4608)
#define S_B1P   (S_WIHP + 16384)
#define S_B2P   (S_B1P + 32)
#define S_B1T   (S_B2P + 32)
#define S_B2T   (S_B1T + 32)
#define S_PRB   (S_B2T + 32)
#define S_BSUM  (S_PRB + 64)
#define S_FW    (S_BSUM + 256)
#define S_FB    (S_FW + 8)
#define S_WARP  (S_FB + 8)

#define PW_XS    0
#define PW_H1    240
#define PW_CAT   1072
#define PW_FEAT  1232
#define PW_SIZE  1360
#define SMEM_FLOATS (S_WARP + ENC_WARPS * PW_SIZE)
#define SMEM_BYTES  (SMEM_FLOATS * 4)

// ---------------------------------------------------------------------------
__global__ void init_kernel() {
    int i = threadIdx.x;
    if (i < TT) g_prog[i] = 0u;
    if (i == 0) g_ticket = 0u;
}

// ---------------------------------------------------------------------------
// Encoder pass, f32x2 paired over input channels. Warp = one window.
// ---------------------------------------------------------------------------
template<int ICP>
__device__ __forceinline__ void encode_f2(
    const float* __restrict__ xs2,
    const ull* __restrict__ w1p, const float* __restrict__ b1s,
    const ull* __restrict__ w2p, const float* __restrict__ b2s,
    float* __restrict__ h12,
    float* __restrict__ outp, int lane)
{
    {
        ull acc[LL1];
        ull binit = pk2(b1s[lane], 0.f);
        #pragma unroll
        for (int p = 0; p < LL1; p++) acc[p] = binit;
        #pragma unroll 2
        for (int icp = 0; icp < ICP; icp++) {
            ull xv[WW];
            const ulonglong2* xp = (const ulonglong2*)(xs2 + icp * 40);
            #pragma unroll
            for (int q = 0; q < 10; q++) { ulonglong2 t = xp[q]; xv[2*q] = t.x; xv[2*q+1] = t.y; }
            const ull* wb_ = w1p + icp * 96;
            ull w0 = wb_[lane], w1 = wb_[32 + lane], w2 = wb_[64 + lane];
            #pragma unroll
            for (int p = 0; p < LL1; p++) {
                fma2(acc[p], xv[p],     w0);
                fma2(acc[p], xv[p + 1], w1);
                fma2(acc[p], xv[p + 2], w2);
            }
        }
        float* dst = h12 + (lane >> 1) * 52 + (lane & 1);
        #pragma unroll
        for (int p = 0; p < LL1; p++) {
            float2 r = unpk(acc[p]);
            dst[2 * p] = fmaxf(r.x + r.y, 0.f);
        }
    }
    __syncwarp();
    {
        ull acc[LL2];
        ull binit = pk2(b2s[lane], 0.f);
        #pragma unroll
        for (int p = 0; p < LL2; p++) acc[p] = binit;
        #pragma unroll 2
        for (int icp = 0; icp < 16; icp++) {
            ull hv[LL1];
            const ulonglong2* hp = (const ulonglong2*)(h12 + icp * 52);
            #pragma unroll
            for (int q = 0; q < 9; q++) { ulonglong2 t = hp[q]; hv[2*q] = t.x; hv[2*q+1] = t.y; }
            const ull* wb_ = w2p + icp * 96;
            ull w0 = wb_[lane], w1 = wb_[32 + lane], w2 = wb_[64 + lane];
            #pragma unroll
            for (int p = 0; p < LL2; p++) {
                fma2(acc[p], hv[p],     w0);
                fma2(acc[p], hv[p + 1], w1);
                fma2(acc[p], hv[p + 2], w2);
            }
        }
        float sum = 0.f;
        #pragma unroll
        for (int p = 0; p < LL2; p++) {
            float2 r = unpk(acc[p]);
            sum += fmaxf(r.x + r.y, 0.f);
        }
        outp[lane] = sum * (1.f / 16.f);
    }
    __syncwarp();
}

// ---------------------------------------------------------------------------
__global__ __launch_bounds__(NTHREADS, 1) void fused_kernel(
    const float* __restrict__ pressure, const float* __restrict__ torque,
    const float* __restrict__ frag,
    const float* __restrict__ pw1, const float* __restrict__ pb1,
    const float* __restrict__ pw2, const float* __restrict__ pb2,
    const float* __restrict__ tw1, const float* __restrict__ tb1,
    const float* __restrict__ tw2, const float* __restrict__ tb2,
    const float* __restrict__ fw,  const float* __restrict__ fb,
    const float* __restrict__ prw, const float* __restrict__ prb,
    const float* __restrict__ Wih, const float* __restrict__ bih,
    const float* __restrict__ bhh, const float* __restrict__ Whh,
    const float* __restrict__ hw,  const float* __restrict__ hb,
    float* __restrict__ out)
{
    extern __shared__ __align__(16) float sm[];
    const int tid = threadIdx.x;
    const int bid = blockIdx.x;

    if (bid >= LSTM_BLOCKS) {
        // =================== ENCODER BLOCK ===================
        const int warp = tid >> 5, lane = tid & 31;

        for (int i = tid; i < 576; i += NTHREADS) {
            int half = i & 1, j = i >> 1, ln = j & 31, q = j >> 5;
            int t = q % 3, icp = q / 3, ic = 2 * icp + half;
            sm[S_W1P + i] = pw1[ln * (NP * 3) + ic * 3 + t];
        }
        for (int i = tid; i < 3072; i += NTHREADS) {
            int half = i & 1, j = i >> 1, ln = j & 31, q = j >> 5;
            int t = q % 3, icp = q / 3, ic = 2 * icp + half;
            sm[S_W2P + i] = pw2[ln * (CH * 3) + ic * 3 + t];
        }
        for (int i = tid; i < 1152; i += NTHREADS) {
            int half = i & 1, j = i >> 1, ln = j & 31, q = j >> 5;
            int t = q % 3, icp = q / 3, ic = 2 * icp + half;
            sm[S_W1T + i] = tw1[ln * (NT * 3) + ic * 3 + t];
        }
        for (int i = tid; i < 3072; i += NTHREADS) {
            int half = i & 1, j = i >> 1, ln = j & 31, q = j >> 5;
            int t = q % 3, icp = q / 3, ic = 2 * icp + half;
            sm[S_W2T + i] = tw2[ln * (CH * 3) + ic * 3 + t];
        }
        for (int i = tid; i < 4608; i += NTHREADS) {
            int half = i & 1, j = i >> 1, jc = j & 63, kp = j >> 6;
            sm[S_PRWP + i] = prw[jc * 72 + 2 * kp + half];
        }
        for (int i = tid; i < 16384; i += NTHREADS) {
            int half = i & 1, j = i >> 1, g = j & 255, kp = j >> 8;
            sm[S_WIHP + i] = Wih[g * 64 + 2 * kp + half];
        }
        if (tid < 32) {
            sm[S_B1P + tid] = pb1[tid];
            sm[S_B2P + tid] = pb2[tid];
            sm[S_B1T + tid] = tb1[tid];
            sm[S_B2T + tid] = tb2[tid];
        }
        if (tid < 64) sm[S_PRB + tid] = prb[tid];
        if (tid < GATES) sm[S_BSUM + tid] = bih[tid] + bhh[tid];
        if (tid < 8) { sm[S_FW + tid] = fw[tid]; sm[S_FB + tid] = fb[tid]; }
        __syncthreads();

        float* wbuf  = sm + S_WARP + warp * PW_SIZE;
        float* xs2   = wbuf + PW_XS;
        float* h12   = wbuf + PW_H1;
        float* cat0  = wbuf + PW_CAT;
        float* cat1  = wbuf + PW_CAT + 80;
        float* feat0 = wbuf + PW_FEAT;
        float* feat1 = wbuf + PW_FEAT + 64;

        int dp[4], dt[8];
        #pragma unroll
        for (int k = 0; k < 4; k++) {
            int i = lane + 32 * k;
            if (i < WW * NP) { int l = i / NP, c = i % NP; dp[k] = (c >> 1) * 40 + 2 * l + (c & 1); }
            else dp[k] = -1;
        }
        #pragma unroll
        for (int k = 0; k < 8; k++) {
            int i = lane + 32 * k;
            if (i < WW * NT) { int l = i / NT, c = i % NT; dt[k] = (c >> 1) * 40 + 2 * l + (c & 1); }
            else dt[k] = -1;
        }

        const ull* w1pp = (const ull*)(sm + S_W1P);
        const ull* w2pp = (const ull*)(sm + S_W2P);
        const ull* w1tp = (const ull*)(sm + S_W1T);
        const ull* w2tp = (const ull*)(sm + S_W2T);

        for (;;) {
            // grab 2 windows (same timestep, adjacent batch rows)
            unsigned m;
            if (lane == 0) m = atomicAdd(&g_ticket, 2u);
            m = __shfl_sync(0xffffffffu, m, 0);
            if (m >= NWIN) break;
            const int t  = m >> 6;
            const int b0 = m & 63;
            const int n0 = b0 * TT + t;
            const int n1 = n0 + TT;

            #pragma unroll 1
            for (int w = 0; w < 2; w++) {
                const int n = (w == 0) ? n0 : n1;
                const int b = b0 + w;
                float* cats = (w == 0) ? cat0 : cat1;
                {
                    const float* src = pressure + (size_t)n * (WW * NP);
                    #pragma unroll
                    for (int k = 0; k < 4; k++)
                        if (dp[k] >= 0) xs2[dp[k]] = src[lane + 32 * k];
                }
                __syncwarp();
                encode_f2<NP/2>(xs2, w1pp, sm + S_B1P, w2pp, sm + S_B2P, h12, cats, lane);
                {
                    const float* src = torque + (size_t)n * (WW * NT);
                    #pragma unroll
                    for (int k = 0; k < 8; k++)
                        if (dt[k] >= 0) xs2[dt[k]] = src[lane + 32 * k];
                }
                __syncwarp();
                encode_f2<NT/2>(xs2, w1tp, sm + S_B1T, w2tp, sm + S_B2T, h12, cats + CH, lane);
                if (lane < 8) {
                    float fv = __ldg(frag + b);
                    cats[2 * CH + lane] = fmaxf(fv * sm[S_FW + lane] + sm[S_FB + lane], 0.f);
                }
                __syncwarp();
            }

            // projection 72 -> 64 (relu), both windows
            {
                ull a00 = pk2(sm[S_PRB + lane], 0.f);
                ull a01 = pk2(sm[S_PRB + lane + 32], 0.f);
                ull a10 = a00, a11 = a01;
                const ull* c0 = (const ull*)cat0;
                const ull* c1 = (const ull*)cat1;
                const ull* pp = (const ull*)(sm + S_PRWP);
                #pragma unroll 6
                for (int kp = 0; kp < 36; kp++) {
                    ull w0 = pp[kp * 64 + lane];
                    ull w1 = pp[kp * 64 + lane + 32];
                    ull cv0 = c0[kp], cv1 = c1[kp];
                    fma2(a00, cv0, w0); fma2(a01, cv0, w1);
                    fma2(a10, cv1, w0); fma2(a11, cv1, w1);
                }
                float2 r;
                r = unpk(a00); feat0[lane]      = fmaxf(r.x + r.y, 0.f);
                r = unpk(a01); feat0[lane + 32] = fmaxf(r.x + r.y, 0.f);
                r = unpk(a10); feat1[lane]      = fmaxf(r.x + r.y, 0.f);
                r = unpk(a11); feat1[lane + 32] = fmaxf(r.x + r.y, 0.f);
            }
            __syncwarp();

            // xg for both windows
            {
                ull acc0[8], acc1[8];
                #pragma unroll
                for (int u = 0; u < 8; u++) {
                    ull bi = pk2(sm[S_BSUM + lane + 32 * u], 0.f);
                    acc0[u] = bi; acc1[u] = bi;
                }
                const ull* f0 = (const ull*)feat0;
                const ull* f1 = (const ull*)feat1;
                const ull* wp = (const ull*)(sm + S_WIHP);
                #pragma unroll 2
                for (int kp = 0; kp < 32; kp++) {
                    ull fv0 = f0[kp], fv1 = f1[kp];
                    #pragma unroll
                    for (int u = 0; u < 8; u++) {
                        ull wv = wp[kp * 256 + lane + 32 * u];
                        fma2(acc0[u], fv0, wv);
                        fma2(acc1[u], fv1, wv);
                    }
                }
                float* xg0 = g_xg + (size_t)n0 * GATES;
                float* xg1 = g_xg + (size_t)n1 * GATES;
                #pragma unroll
                for (int u = 0; u < 8; u++) {
                    float2 r0 = unpk(acc0[u]);
                    float2 r1 = unpk(acc1[u]);
                    xg0[lane + 32 * u] = r0.x + r0.y;
                    xg1[lane + 32 * u] = r1.x + r1.y;
                }
            }
            // publish: all lanes fence, then one release-increment
            __threadfence();
            __syncwarp();
            if (lane == 0) red_rel_add(&g_prog[t], 2u);
        }
        return;
    }

    // =================== LSTM BLOCK (2 batch rows) ===================
    const int half  = tid >> 8;          // 0 or 1: which row
    const int r_tid = tid & 255;         // gate index within row
    const int b     = bid * 2 + half;
    const int wl    = r_tid >> 5, l = r_tid & 31;

    // smem: h_s[half][buf][64] then g_sh[half][256]
    float* hs   = sm + half * 128;
    float* gsh  = sm + 256 + half * 256;

    ull whh2[32];
    const ulonglong2* wr = (const ulonglong2*)(Whh + r_tid * PROJD);
    #pragma unroll
    for (int k = 0; k < 16; k++) {
        ulonglong2 t = wr[k];
        whh2[2 * k] = t.x; whh2[2 * k + 1] = t.y;
    }

    const int hk = l >> 3, hi = l & 7;
    float hwreg[8]; float hbk = 0.f;
    if (wl == 2) {
        #pragma unroll
        for (int qq = 0; qq < 8; qq++) hwreg[qq] = __ldg(hw + hk * PROJD + hi * 8 + qq);
        hbk = __ldg(hb + hk);
    }

    if (r_tid < PROJD) hs[r_tid] = 0.f;    // buffer 0
    float c = 0.f, hn = 0.f;
    __syncthreads();

    const float* xgb = g_xg + (size_t)b * TT * GATES + r_tid;
    float* outb = out + (size_t)b * TT * 4;

    bool havenext = false;
    float xnext = 0.f;

    for (int ts = 0; ts < TT; ts++) {
        float xcur;
        if (havenext) {
            xcur = xnext;
        } else {
            while (ld_acq(&g_prog[ts]) < 64u) __nanosleep(64);
            xcur = ld_strong(xgb + (size_t)ts * GATES);
        }
        // early non-blocking readiness check for ts+1 (latency hidden by dot)
        unsigned pnext = 0;
        if (ts + 1 < TT) pnext = ld_acq(&g_prog[ts + 1]);

        ull a0 = pk2(xcur, 0.f), a1 = pk2(0.f, 0.f);
        ull a2 = pk2(0.f, 0.f),  a3 = pk2(0.f, 0.f);
        const ulonglong2* hp = (const ulonglong2*)(hs + (ts & 1) * PROJD);
        #pragma unroll
        for (int k = 0; k < 8; k++) {
            ulonglong2 h01 = hp[2 * k], h23 = hp[2 * k + 1];
            fma2(a0, h01.x, whh2[4 * k]);
            fma2(a1, h01.y, whh2[4 * k + 1]);
            fma2(a2, h23.x, whh2[4 * k + 2]);
            fma2(a3, h23.y, whh2[4 * k + 3]);
        }
        float2 r = unpk(add2(add2(a0, a1), add2(a2, a3)));
        gsh[r_tid] = r.x + r.y;

        // speculative prefetch (overlaps barrier + act phase)
        havenext = false;
        if (pnext >= 64u) {
            xnext = ld_strong(xgb + (size_t)(ts + 1) * GATES);
            havenext = true;
        }
        __syncthreads();
        if (r_tid < PROJD) {
            float iv = gsh[r_tid], fv = gsh[r_tid + 64];
            float gg = gsh[r_tid + 128], ov = gsh[r_tid + 192];
            c = sig_t(fv) * c + sig_t(iv) * tanhx(gg);
            hn = sig_t(ov) * tanhx(c);
            hs[((ts + 1) & 1) * PROJD + r_tid] = hn;   // write NEXT buffer
        } else if (wl == 2 && ts > 0) {
            const float* hprev = hs + (ts & 1) * PROJD;  // stable buffer
            float s = 0.f;
            #pragma unroll
            for (int qq = 0; qq < 8; qq++) s += hprev[hi * 8 + qq] * hwreg[qq];
            s += __shfl_xor_sync(0xffffffffu, s, 1);
            s += __shfl_xor_sync(0xffffffffu, s, 2);
            s += __shfl_xor_sync(0xffffffffu, s, 4);
            if (hi == 0) outb[(ts - 1) * 4 + hk] = sig_t(s + hbk);
        }
        __syncthreads();
    }
    // final head step
    if (wl == 2) {
        const float* hprev = hs + (TT & 1) * PROJD;
        float s = 0.f;
        #pragma unroll
        for (int qq = 0; qq < 8; qq++) s += hprev[hi * 8 + qq] * hwreg[qq];
        s += __shfl_xor_sync(0xffffffffu, s, 1);
        s += __shfl_xor_sync(0xffffffffu, s, 2);
        s += __shfl_xor_sync(0xffffffffu, s, 4);
        if (hi == 0) outb[(TT - 1) * 4 + hk] = sig_t(s + hbk);
    }
    if (r_tid < PROJD) {
        out[NWIN * 4 + b * PROJD + r_tid] = hn;                  // hT
        out[NWIN * 4 + BB * PROJD + b * PROJD + r_tid] = c;      // cT
    }
}

// ---------------------------------------------------------------------------
extern "C" void kernel_launch(void* const* d_in, const int* in_sizes, int n_in,
                              void* d_out, int out_size)
{
    const float* pressure = (const float*)d_in[0];
    const float* torque   = (const float*)d_in[1];
    const float* frag     = (const float*)d_in[2];
    const float* pw1 = (const float*)d_in[3];
    const float* pb1 = (const float*)d_in[4];
    const float* pw2 = (const float*)d_in[5];
    const float* pb2 = (const float*)d_in[6];
    const float* tw1 = (const float*)d_in[7];
    const float* tb1 = (const float*)d_in[8];
    const float* tw2 = (const float*)d_in[9];
    const float* tb2 = (const float*)d_in[10];
    const float* fw  = (const float*)d_in[11];
    const float* fb  = (const float*)d_in[12];
    const float* prw = (const float*)d_in[13];
    const float* prb = (const float*)d_in[14];
    const float* Wih = (const float*)d_in[15];
    const float* Whh = (const float*)d_in[16];
    const float* bih = (const float*)d_in[17];
    const float* bhh = (const float*)d_in[18];
    const float* hw  = (const float*)d_in[19];
    const float* hb  = (const float*)d_in[20];
    float* out = (float*)d_out;

    cudaFuncSetAttribute(fused_kernel,
                         cudaFuncAttributeMaxDynamicSharedMemorySize, SMEM_BYTES);

    init_kernel<<<1, 256>>>();
    fused_kernel<<<GRID_BLOCKS, NTHREADS, SMEM_BYTES>>>(
        pressure, torque, frag,
        pw1, pb1, pw2, pb2, tw1, tb1, tw2, tb2,
        fw, fb, prw, prb, Wih, bih, bhh, Whh, hw, hb, out);
}